// round 5
// baseline (speedup 1.0000x reference)
#include <cuda_runtime.h>
#include <cuda_bf16.h>
#include <cstdint>

// ---------------------------------------------------------------------------
// B=8192, D=256.
// loss = -sum_ij log_sigmoid(y_ij * (che_i . loc_j * exp(t') + b)) / B
// y = +1 diag, -1 off-diag.
// mma.sync m16n8k16 bf16 path (harness PTX target compute_103, no tcgen05).
//
// R5: persistent work-stealing CTAs, 256x128 tile, 8 warps of 64x64 frags,
//     two half-K (128) SMEM buffers double-buffered across tiles via cp.async.
// ---------------------------------------------------------------------------

#define BATCH  8192
#define DIM    256
#define TM     256
#define TN     128
#define NTILES ((BATCH / TM) * (BATCH / TN))   // 32*64 = 2048

// Half-K buffer: 384 rows x 128 bf16 (256B) + 16B pad = 272B row stride.
// 272 = 68 words; 68 mod 32 = 4 -> 8 consecutive rows hit distinct banks;
// 272 % 16 == 0 keeps ldmatrix 16B alignment.
#define ROWB 272
#define HALF_BYTES (384 * ROWB)                // 104448
#define SMEM_TOTAL (2 * HALF_BYTES)            // 208896

// Scratch (device globals; no allocation allowed)
__device__ __nv_bfloat16 g_che[BATCH * DIM];
__device__ __nv_bfloat16 g_loc[BATCH * DIM];
__device__ float g_scale;
__device__ float g_shift;
__device__ float g_acc;
__device__ unsigned g_tile_ctr;

__device__ __forceinline__ uint32_t smem_u32(const void* p) {
    uint32_t a;
    asm("{ .reg .u64 t; cvta.to.shared.u64 t, %1; cvt.u32.u64 %0, t; }"
        : "=r"(a) : "l"(p));
    return a;
}

__device__ __forceinline__ void ldmatrix_x4(uint32_t* r, uint32_t addr) {
    asm volatile("ldmatrix.sync.aligned.m8n8.x4.shared.b16 {%0,%1,%2,%3}, [%4];"
                 : "=r"(r[0]), "=r"(r[1]), "=r"(r[2]), "=r"(r[3])
                 : "r"(addr));
}

__device__ __forceinline__ void mma_bf16(float* c, const uint32_t* a,
                                         uint32_t b0, uint32_t b1) {
    asm volatile(
        "mma.sync.aligned.m16n8k16.row.col.f32.bf16.bf16.f32 "
        "{%0,%1,%2,%3}, {%4,%5,%6,%7}, {%8,%9}, {%0,%1,%2,%3};"
        : "+f"(c[0]), "+f"(c[1]), "+f"(c[2]), "+f"(c[3])
        : "r"(a[0]), "r"(a[1]), "r"(a[2]), "r"(a[3]), "r"(b0), "r"(b1));
}

#define CP_ASYNC16(dst, src) \
    asm volatile("cp.async.cg.shared.global [%0], [%1], 16;" \
                 :: "r"(dst), "l"(src) : "memory")
#define CP_COMMIT() asm volatile("cp.async.commit_group;" ::: "memory")
#define CP_WAIT(n)  asm volatile("cp.async.wait_group %0;" :: "n"(n) : "memory")

// ---------------------------------------------------------------------------
// Kernel 1: row L2-normalize -> bf16 scratch. 2 rows per warp (MLP).
// grid = BATCH/16 blocks of 256 threads.
// ---------------------------------------------------------------------------
__global__ __launch_bounds__(256)
void norm_kernel(const float* __restrict__ loc,
                 const float* __restrict__ che,
                 const float* __restrict__ t_prime,
                 const float* __restrict__ b_in)
{
    int warp = threadIdx.x >> 5;
    int lane = threadIdx.x & 31;
    int row0 = (blockIdx.x << 4) + (warp << 1);

    #pragma unroll
    for (int rr = 0; rr < 2; rr++) {
        int row = row0 + rr;
        const float4* l4 = reinterpret_cast<const float4*>(loc + row * DIM) + lane * 2;
        const float4* c4 = reinterpret_cast<const float4*>(che + row * DIM) + lane * 2;
        float4 a0 = l4[0], a1 = l4[1];
        float4 b0 = c4[0], b1 = c4[1];

        float s0 = a0.x*a0.x + a0.y*a0.y + a0.z*a0.z + a0.w*a0.w
                 + a1.x*a1.x + a1.y*a1.y + a1.z*a1.z + a1.w*a1.w;
        float s1 = b0.x*b0.x + b0.y*b0.y + b0.z*b0.z + b0.w*b0.w
                 + b1.x*b1.x + b1.y*b1.y + b1.z*b1.z + b1.w*b1.w;
        #pragma unroll
        for (int o = 16; o > 0; o >>= 1) {
            s0 += __shfl_xor_sync(0xFFFFFFFFu, s0, o);
            s1 += __shfl_xor_sync(0xFFFFFFFFu, s1, o);
        }
        float r0 = rsqrtf(s0);
        float r1 = rsqrtf(s1);

        __nv_bfloat162 h[4];
        h[0] = __float22bfloat162_rn(make_float2(a0.x*r0, a0.y*r0));
        h[1] = __float22bfloat162_rn(make_float2(a0.z*r0, a0.w*r0));
        h[2] = __float22bfloat162_rn(make_float2(a1.x*r0, a1.y*r0));
        h[3] = __float22bfloat162_rn(make_float2(a1.z*r0, a1.w*r0));
        *reinterpret_cast<uint4*>(g_loc + row * DIM + lane * 8) =
            *reinterpret_cast<uint4*>(h);

        h[0] = __float22bfloat162_rn(make_float2(b0.x*r1, b0.y*r1));
        h[1] = __float22bfloat162_rn(make_float2(b0.z*r1, b0.w*r1));
        h[2] = __float22bfloat162_rn(make_float2(b1.x*r1, b1.y*r1));
        h[3] = __float22bfloat162_rn(make_float2(b1.z*r1, b1.w*r1));
        *reinterpret_cast<uint4*>(g_che + row * DIM + lane * 8) =
            *reinterpret_cast<uint4*>(h);
    }

    if (blockIdx.x == 0 && threadIdx.x == 0) {
        g_scale = expf(t_prime[0]);
        g_shift = b_in[0];
        g_acc = 0.0f;
        g_tile_ctr = 0u;
    }
}

// ---------------------------------------------------------------------------
// GEMM helpers
// ---------------------------------------------------------------------------
__device__ __forceinline__ void prefetch_half(uint32_t dstBase, int m0, int n0,
                                              int h, int tid)
{
    const uint4* cheq = reinterpret_cast<const uint4*>(g_che);
    const uint4* locq = reinterpret_cast<const uint4*>(g_loc);
    #pragma unroll
    for (int it = 0; it < 24; it++) {
        int idx = it * 256 + tid;            // 0..6143
        int r = idx >> 4;                    // 0..383
        int cl = idx & 15;                   // local 16B chunk
        int cg = cl + h * 16;                // global chunk 0..31
        uint32_t dst = dstBase + (uint32_t)(r * ROWB + cl * 16);
        const uint4* src = (r < TM) ? &cheq[(m0 + r) * 32 + cg]
                                    : &locq[(n0 + r - TM) * 32 + cg];
        CP_ASYNC16(dst, src);
    }
}

__device__ __forceinline__ void compute_half(uint32_t base,
                                             const uint32_t* aOff,
                                             const uint32_t* bOff,
                                             float (*c)[4])
{
    #pragma unroll
    for (int ks = 0; ks < 8; ks++) {
        uint32_t koff = (uint32_t)(ks * 32);
        uint32_t a[4][4], b[4][4];
        #pragma unroll
        for (int i = 0; i < 4; i++) ldmatrix_x4(a[i], base + aOff[i] + koff);
        #pragma unroll
        for (int q = 0; q < 4; q++) ldmatrix_x4(b[q], base + bOff[q] + koff);
        #pragma unroll
        for (int mt = 0; mt < 4; mt++) {
            #pragma unroll
            for (int nt = 0; nt < 8; nt++) {
                uint32_t b0 = b[nt >> 1][(nt & 1) ? 2 : 0];
                uint32_t b1 = b[nt >> 1][(nt & 1) ? 3 : 1];
                mma_bf16(c[mt * 8 + nt], a[mt], b0, b1);
            }
        }
    }
}

// ---------------------------------------------------------------------------
// Kernel 2: persistent 256x128-tile GEMM + fused softplus epilogue.
// 8 warps, warp (wy,wx) = (wid>>1, wid&1) computes 64x64.
// ---------------------------------------------------------------------------
__global__ __launch_bounds__(256, 1)
void gemm_loss_kernel()
{
    extern __shared__ __align__(16) char smem[];
    const uint32_t sBase = smem_u32(smem);

    __shared__ unsigned sh_next;
    __shared__ float shred[8];

    int tid = threadIdx.x;
    int wid = tid >> 5;
    int lane = tid & 31;

    int am = (wid >> 1) * 64;
    int bn = (wid & 1) * 64;

    // ldmatrix byte offsets (relative to half-buffer base)
    uint32_t aOff[4], bOff[4];
    #pragma unroll
    for (int i = 0; i < 4; i++)
        aOff[i] = (uint32_t)((am + i * 16 + (lane & 15)) * ROWB
                             + ((lane >> 4) << 4));
    uint32_t bRow = (uint32_t)(((lane >> 4) << 3) + (lane & 7));
    uint32_t bCol = (uint32_t)((((lane >> 3) & 1)) << 4);
    #pragma unroll
    for (int q = 0; q < 4; q++)
        bOff[q] = (uint32_t)((TM + bn + q * 16 + bRow) * ROWB) + bCol;

    float c[32][4];
    #pragma unroll
    for (int i = 0; i < 32; i++)
        #pragma unroll
        for (int j = 0; j < 4; j++) c[i][j] = 0.0f;

    float scale = g_scale;
    float shift = g_shift;
    float acc = 0.0f;

    // ---- first tile ----
    if (tid == 0) sh_next = atomicAdd(&g_tile_ctr, 1u);
    __syncthreads();
    unsigned t = sh_next;
    if (t >= NTILES) return;   // uniform exit for surplus CTAs

    int m0 = (int)(t & 31) * TM;
    int n0 = (int)(t >> 5) * TN;
    prefetch_half(sBase, m0, n0, 0, tid);
    CP_COMMIT();
    prefetch_half(sBase + HALF_BYTES, m0, n0, 1, tid);
    CP_COMMIT();

    for (;;) {
        // buf0 (half 0 of t) ready after this wait
        CP_WAIT(1);
        __syncthreads();                       // sync1
        if (tid == 0) sh_next = atomicAdd(&g_tile_ctr, 1u);

        compute_half(sBase, aOff, bOff, c);
        __syncthreads();                       // sync2: buf0 free, sh_next valid
        unsigned u = sh_next;
        int um0 = (int)(u & 31) * TM;
        int un0 = (int)(u >> 5) * TN;

        if (u < NTILES) prefetch_half(sBase, um0, un0, 0, tid);
        CP_COMMIT();

        CP_WAIT(1);                            // buf1 (half 1 of t) ready
        __syncthreads();                       // sync3
        compute_half(sBase + HALF_BYTES, aOff, bOff, c);
        __syncthreads();                       // sync4: buf1 free
        if (u < NTILES) prefetch_half(sBase + HALF_BYTES, um0, un0, 1, tid);
        CP_COMMIT();

        // ---- epilogue for tile t (overlaps u's loads) ----
        int rbase = m0 + am + (lane >> 2);
        int cbase = n0 + bn + (lane & 3) * 2;
        #pragma unroll
        for (int mt = 0; mt < 4; mt++) {
            #pragma unroll
            for (int nt = 0; nt < 8; nt++) {
                float* cc = c[mt * 8 + nt];
                int col0 = cbase + nt * 8;
                #pragma unroll
                for (int j = 0; j < 4; j++) {
                    int row = rbase + mt * 16 + ((j >> 1) << 3);
                    int col = col0 + (j & 1);
                    float z = fmaf(cc[j], scale, shift);
                    float v = (row == col) ? z : -z;     // y*z
                    float av = fabsf(v);
                    float e = __expf(-av);
                    float l;
                    if (e < 0.0625f) {
                        // log1p(e) ~ e - e^2/2 + e^3/3, |err| <= e^4/4
                        l = e * fmaf(e, fmaf(e, 0.33333333f, -0.5f), 1.0f);
                    } else {
                        l = log1pf(e);                   // near-diagonal only
                    }
                    acc += fmaxf(-v, 0.0f) + l;          // softplus(-v)
                    cc[j] = 0.0f;                        // reset accumulator
                }
            }
        }

        if (u >= NTILES) break;
        t = u; m0 = um0; n0 = un0;
    }

    // ---- CTA-wide reduce + one atomic ----
    #pragma unroll
    for (int o = 16; o > 0; o >>= 1)
        acc += __shfl_xor_sync(0xFFFFFFFFu, acc, o);
    if (lane == 0) shred[wid] = acc;
    __syncthreads();
    if (tid == 0) {
        float s = 0.f;
        #pragma unroll
        for (int i = 0; i < 8; i++) s += shred[i];
        atomicAdd(&g_acc, s);
    }
}

// ---------------------------------------------------------------------------
// g_acc = sum_ij -log_sigmoid(y*z)  ->  loss = +g_acc/B
// ---------------------------------------------------------------------------
__global__ void finalize_kernel(float* out)
{
    out[0] = g_acc * (1.0f / (float)BATCH);
}

// ---------------------------------------------------------------------------
extern "C" void kernel_launch(void* const* d_in, const int* in_sizes, int n_in,
                              void* d_out, int out_size)
{
    const float* loc = (const float*)d_in[0];
    const float* che = (const float*)d_in[1];
    const float* tp  = (const float*)d_in[2];
    const float* bb  = (const float*)d_in[3];
    float* out = (float*)d_out;

    norm_kernel<<<BATCH / 16, 256>>>(loc, che, tp, bb);

    static bool attr_set = false;
    if (!attr_set) {
        cudaFuncSetAttribute(gemm_loss_kernel,
                             cudaFuncAttributeMaxDynamicSharedMemorySize, SMEM_TOTAL);
        attr_set = true;
    }
    gemm_loss_kernel<<<192, 256, SMEM_TOTAL>>>();

    finalize_kernel<<<1, 1>>>(out);
}

// round 6
// speedup vs baseline: 1.0003x; 1.0003x over previous
#include <cuda_runtime.h>
#include <cuda_bf16.h>
#include <cstdint>

// ---------------------------------------------------------------------------
// B=8192, D=256.
// loss = -sum_ij log_sigmoid(y_ij * (che_i . loc_j * exp(t') + b)) / B
// y = +1 diag, -1 off-diag.
// mma.sync m16n8k16 bf16 (harness PTX target compute_103; no tcgen05).
//
// R6: persistent CTAs (152), 256 threads, 256x128 tiles, 8 warps of 64x64,
//     K split into 4 chunks of 64, 4-buffer SW128-swizzled ring, cp.async
//     prefetch 3 chunks ahead, 1 barrier per chunk.
// ---------------------------------------------------------------------------

#define BATCH  8192
#define DIM    256
#define TM     256
#define TN     128
#define NTILES ((BATCH / TM) * (BATCH / TN))   // 2048

#define CHUNK_BYTES (384 * 128)                // 384 rows x 64 bf16 (128B), dense
#define SMEM_TOTAL  (4 * CHUNK_BYTES)          // 196608

// Scratch (device globals; no allocation allowed)
__device__ __nv_bfloat16 g_che[BATCH * DIM];
__device__ __nv_bfloat16 g_loc[BATCH * DIM];
__device__ float g_scale;
__device__ float g_shift;
__device__ float g_acc;
__device__ unsigned g_tile_ctr;

__device__ __forceinline__ uint32_t smem_u32(const void* p) {
    uint32_t a;
    asm("{ .reg .u64 t; cvta.to.shared.u64 t, %1; cvt.u32.u64 %0, t; }"
        : "=r"(a) : "l"(p));
    return a;
}

__device__ __forceinline__ void ldmatrix_x4(uint32_t* r, uint32_t addr) {
    asm volatile("ldmatrix.sync.aligned.m8n8.x4.shared.b16 {%0,%1,%2,%3}, [%4];"
                 : "=r"(r[0]), "=r"(r[1]), "=r"(r[2]), "=r"(r[3])
                 : "r"(addr));
}

__device__ __forceinline__ void mma_bf16(float* c, const uint32_t* a,
                                         uint32_t b0, uint32_t b1) {
    asm volatile(
        "mma.sync.aligned.m16n8k16.row.col.f32.bf16.bf16.f32 "
        "{%0,%1,%2,%3}, {%4,%5,%6,%7}, {%8,%9}, {%0,%1,%2,%3};"
        : "+f"(c[0]), "+f"(c[1]), "+f"(c[2]), "+f"(c[3])
        : "r"(a[0]), "r"(a[1]), "r"(a[2]), "r"(a[3]), "r"(b0), "r"(b1));
}

#define CP_ASYNC16(dst, src) \
    asm volatile("cp.async.cg.shared.global [%0], [%1], 16;" \
                 :: "r"(dst), "l"(src) : "memory")
#define CP_COMMIT() asm volatile("cp.async.commit_group;" ::: "memory")
#define CP_WAIT(n)  asm volatile("cp.async.wait_group %0;" :: "n"(n) : "memory")

// ---------------------------------------------------------------------------
// Kernel 1: row L2-normalize -> bf16 scratch. 2 rows per warp.
// ---------------------------------------------------------------------------
__global__ __launch_bounds__(256)
void norm_kernel(const float* __restrict__ loc,
                 const float* __restrict__ che,
                 const float* __restrict__ t_prime,
                 const float* __restrict__ b_in)
{
    int warp = threadIdx.x >> 5;
    int lane = threadIdx.x & 31;
    int row0 = (blockIdx.x << 4) + (warp << 1);

    #pragma unroll
    for (int rr = 0; rr < 2; rr++) {
        int row = row0 + rr;
        const float4* l4 = reinterpret_cast<const float4*>(loc + row * DIM) + lane * 2;
        const float4* c4 = reinterpret_cast<const float4*>(che + row * DIM) + lane * 2;
        float4 a0 = l4[0], a1 = l4[1];
        float4 b0 = c4[0], b1 = c4[1];

        float s0 = a0.x*a0.x + a0.y*a0.y + a0.z*a0.z + a0.w*a0.w
                 + a1.x*a1.x + a1.y*a1.y + a1.z*a1.z + a1.w*a1.w;
        float s1 = b0.x*b0.x + b0.y*b0.y + b0.z*b0.z + b0.w*b0.w
                 + b1.x*b1.x + b1.y*b1.y + b1.z*b1.z + b1.w*b1.w;
        #pragma unroll
        for (int o = 16; o > 0; o >>= 1) {
            s0 += __shfl_xor_sync(0xFFFFFFFFu, s0, o);
            s1 += __shfl_xor_sync(0xFFFFFFFFu, s1, o);
        }
        float r0 = rsqrtf(s0);
        float r1 = rsqrtf(s1);

        __nv_bfloat162 h[4];
        h[0] = __float22bfloat162_rn(make_float2(a0.x*r0, a0.y*r0));
        h[1] = __float22bfloat162_rn(make_float2(a0.z*r0, a0.w*r0));
        h[2] = __float22bfloat162_rn(make_float2(a1.x*r0, a1.y*r0));
        h[3] = __float22bfloat162_rn(make_float2(a1.z*r0, a1.w*r0));
        *reinterpret_cast<uint4*>(g_loc + row * DIM + lane * 8) =
            *reinterpret_cast<uint4*>(h);

        h[0] = __float22bfloat162_rn(make_float2(b0.x*r1, b0.y*r1));
        h[1] = __float22bfloat162_rn(make_float2(b0.z*r1, b0.w*r1));
        h[2] = __float22bfloat162_rn(make_float2(b1.x*r1, b1.y*r1));
        h[3] = __float22bfloat162_rn(make_float2(b1.z*r1, b1.w*r1));
        *reinterpret_cast<uint4*>(g_che + row * DIM + lane * 8) =
            *reinterpret_cast<uint4*>(h);
    }

    if (blockIdx.x == 0 && threadIdx.x == 0) {
        g_scale = expf(t_prime[0]);
        g_shift = b_in[0];
        g_acc = 0.0f;
        g_tile_ctr = 0u;
    }
}

// ---------------------------------------------------------------------------
// Prefetch one K=64 chunk (384 rows x 128B) into a swizzled ring buffer.
// Each thread: 12 cp.async of 16B. Lane-groups of 8 cover one full 128B row
// (all 32 banks) -> conflict-free stores.
// ---------------------------------------------------------------------------
__device__ __forceinline__ void prefetch_chunk(uint32_t dstBase, int m0, int n0,
                                               int chunk, int tid)
{
    const __nv_bfloat16* cheB = g_che + (size_t)m0 * DIM + chunk * 64;
    const __nv_bfloat16* locB = g_loc + (size_t)(n0 - TM) * DIM + chunk * 64;
    #pragma unroll
    for (int it = 0; it < 12; it++) {
        int idx = it * 256 + tid;            // 0..3071
        int r = idx >> 3;                    // 0..383
        int c = idx & 7;                     // 16B slot within 128B row
        uint32_t sw = (uint32_t)((c << 4) ^ ((r & 7) << 4));
        uint32_t dst = dstBase + (uint32_t)(r << 7) + sw;
        const __nv_bfloat16* src = (r < TM) ? cheB + (size_t)r * DIM + c * 8
                                            : locB + (size_t)r * DIM + c * 8;
        CP_ASYNC16(dst, src);
    }
}

// ---------------------------------------------------------------------------
// Compute one K=64 chunk: 4 ks steps of m16n8k16 over this warp's 64x64 frag.
// ---------------------------------------------------------------------------
__device__ __forceinline__ void compute_chunk(uint32_t base,
                                              const uint32_t* aRB, const uint32_t* aX,
                                              const uint32_t* bRB, const uint32_t* bX,
                                              uint32_t kloA, uint32_t kloB,
                                              float (*c)[4])
{
    #pragma unroll
    for (int ks = 0; ks < 4; ks++) {
        uint32_t koff = (uint32_t)(ks << 5);   // 32B per k16 step
        uint32_t a[4][4], b[4][4];
        #pragma unroll
        for (int i = 0; i < 4; i++)
            ldmatrix_x4(a[i], base + aRB[i] + ((koff + kloA) ^ aX[i]));
        #pragma unroll
        for (int q = 0; q < 4; q++)
            ldmatrix_x4(b[q], base + bRB[q] + ((koff + kloB) ^ bX[q]));
        #pragma unroll
        for (int mt = 0; mt < 4; mt++) {
            #pragma unroll
            for (int nt = 0; nt < 8; nt++) {
                uint32_t b0 = b[nt >> 1][(nt & 1) ? 2 : 0];
                uint32_t b1 = b[nt >> 1][(nt & 1) ? 3 : 1];
                mma_bf16(c[mt * 8 + nt], a[mt], b0, b1);
            }
        }
    }
}

// ---------------------------------------------------------------------------
// Kernel 2: persistent 256x128-tile GEMM + fused softplus epilogue.
// 8 warps, warp frag 64x64: am=(wid>>1)*64, bn=(wid&1)*64.
// ---------------------------------------------------------------------------
__global__ __launch_bounds__(256, 1)
void gemm_loss_kernel()
{
    extern __shared__ __align__(128) char smem[];
    const uint32_t sBase = smem_u32(smem);

    __shared__ unsigned sh_next;

    int tid = threadIdx.x;
    int wid = tid >> 5;
    int lane = tid & 31;

    int am = (wid >> 1) * 64;
    int bn = (wid & 1) * 64;

    // ldmatrix addressing components (dense 128B rows + SW128 xor swizzle)
    uint32_t aRB[4], aX[4], bRB[4], bX[4];
    #pragma unroll
    for (int i = 0; i < 4; i++) {
        int r = am + i * 16 + (lane & 15);
        aRB[i] = (uint32_t)(r << 7);
        aX[i]  = (uint32_t)((r & 7) << 4);
    }
    #pragma unroll
    for (int q = 0; q < 4; q++) {
        int r = TM + bn + q * 16 + ((lane >> 4) << 3) + (lane & 7);
        bRB[q] = (uint32_t)(r << 7);
        bX[q]  = (uint32_t)((r & 7) << 4);
    }
    uint32_t kloA = (uint32_t)((lane >> 4) << 4);
    uint32_t kloB = (uint32_t)(((lane >> 3) & 1) << 4);

    float c[32][4];
    #pragma unroll
    for (int i = 0; i < 32; i++)
        #pragma unroll
        for (int j = 0; j < 4; j++) c[i][j] = 0.0f;

    float scale = g_scale;
    float shift = g_shift;
    float acc = 0.0f;

    // ---- grab first tile ----
    if (tid == 0) sh_next = atomicAdd(&g_tile_ctr, 1u);
    __syncthreads();
    unsigned cur = sh_next;
    if (cur >= NTILES) return;

    int m0 = (int)(cur & 31) * TM;
    int n0 = (int)(cur >> 5) * TN;

    // warm ring: chunks 0,1,2 of first tile
    #pragma unroll
    for (int ch = 0; ch < 3; ch++) {
        prefetch_chunk(sBase + (uint32_t)(ch * CHUNK_BYTES), m0, n0, ch, tid);
        CP_COMMIT();
    }

    unsigned nxt = 0;
    for (;;) {
        int nm0 = 0, nn0 = 0;

        #pragma unroll
        for (int k = 0; k < 4; k++) {
            CP_WAIT(2);            // chunk k of cur complete (k+1,k+2 may pend)
            __syncthreads();       // data visible; ring slot k's old data consumed

            if (k == 0) {
                if (tid == 0) sh_next = atomicAdd(&g_tile_ctr, 1u);
                prefetch_chunk(sBase + 3u * CHUNK_BYTES, m0, n0, 3, tid);
            } else {
                if (k == 1) {
                    nxt = sh_next;            // stable: written in k=0, barrier in k=1
                    nm0 = (int)(nxt & 31) * TM;
                    nn0 = (int)(nxt >> 5) * TN;
                }
                if (nxt < NTILES)
                    prefetch_chunk(sBase + (uint32_t)((k - 1) * CHUNK_BYTES),
                                   nm0, nn0, k - 1, tid);
            }
            CP_COMMIT();

            compute_chunk(sBase + (uint32_t)(k * CHUNK_BYTES),
                          aRB, aX, bRB, bX, kloA, kloB, c);
        }

        // ---- epilogue for tile cur (next tile's loads stream meanwhile) ----
        {
            int rbase = m0 + am + (lane >> 2);
            int cbase = n0 + bn + (lane & 3) * 2;
            #pragma unroll
            for (int mt = 0; mt < 4; mt++) {
                #pragma unroll
                for (int nt = 0; nt < 8; nt++) {
                    float* cc = c[mt * 8 + nt];
                    int col0 = cbase + nt * 8;
                    #pragma unroll
                    for (int j = 0; j < 4; j++) {
                        int row = rbase + mt * 16 + ((j >> 1) << 3);
                        int col = col0 + (j & 1);
                        float z = fmaf(cc[j], scale, shift);
                        float v = (row == col) ? z : -z;     // y*z
                        float av = fabsf(v);
                        float e = __expf(-av);
                        float l;
                        if (e < 0.0625f) {
                            // log1p(e) ~ e - e^2/2 + e^3/3, |err| <= e^4/4
                            l = e * fmaf(e, fmaf(e, 0.33333333f, -0.5f), 1.0f);
                        } else {
                            l = log1pf(e);                   // near-diagonal only
                        }
                        acc += fmaxf(-v, 0.0f) + l;          // softplus(-v)
                        cc[j] = 0.0f;
                    }
                }
            }
        }

        if (nxt >= NTILES) break;
        cur = nxt; m0 = (int)(cur & 31) * TM; n0 = (int)(cur >> 5) * TN;
    }

    // ---- CTA reduce + one atomic ----
    #pragma unroll
    for (int o = 16; o > 0; o >>= 1)
        acc += __shfl_xor_sync(0xFFFFFFFFu, acc, o);
    __shared__ float shred[8];
    if (lane == 0) shred[wid] = acc;
    __syncthreads();
    if (tid == 0) {
        float s = 0.f;
        #pragma unroll
        for (int i = 0; i < 8; i++) s += shred[i];
        atomicAdd(&g_acc, s);
    }
}

// ---------------------------------------------------------------------------
// g_acc = sum_ij -log_sigmoid(y*z)  ->  loss = +g_acc/B
// ---------------------------------------------------------------------------
__global__ void finalize_kernel(float* out)
{
    out[0] = g_acc * (1.0f / (float)BATCH);
}

// ---------------------------------------------------------------------------
extern "C" void kernel_launch(void* const* d_in, const int* in_sizes, int n_in,
                              void* d_out, int out_size)
{
    const float* loc = (const float*)d_in[0];
    const float* che = (const float*)d_in[1];
    const float* tp  = (const float*)d_in[2];
    const float* bb  = (const float*)d_in[3];
    float* out = (float*)d_out;

    norm_kernel<<<BATCH / 16, 256>>>(loc, che, tp, bb);

    static bool attr_set = false;
    if (!attr_set) {
        cudaFuncSetAttribute(gemm_loss_kernel,
                             cudaFuncAttributeMaxDynamicSharedMemorySize, SMEM_TOTAL);
        attr_set = true;
    }
    gemm_loss_kernel<<<152, 256, SMEM_TOTAL>>>();

    finalize_kernel<<<1, 1>>>(out);
}

// round 7
// speedup vs baseline: 1.4884x; 1.4879x over previous
#include <cuda_runtime.h>
#include <cuda_bf16.h>
#include <cstdint>

// ---------------------------------------------------------------------------
// B=8192, D=256.
// loss = -sum_ij log_sigmoid(y_ij * (che_i . loc_j * exp(t') + b)) / B
// y = +1 diag, -1 off-diag.
// mma.sync m16n8k16 bf16 (harness PTX target compute_103; no tcgen05).
//
// R7: persistent CTAs (152), 512 threads (16 warps of 64x32 fragments),
//     256x128 tiles, K split into 4 chunks of 64, 4-buffer SW128 ring,
//     cp.async prefetch 3 chunks ahead, 1 barrier per chunk.
//     (R6's schedule was sound; at 8 warps it was latency-bound. 16 warps
//      restores 4 warps/SMSP for hiding LDSM/HMMA latency.)
// ---------------------------------------------------------------------------

#define BATCH  8192
#define DIM    256
#define TM     256
#define TN     128
#define NTILES ((BATCH / TM) * (BATCH / TN))   // 2048

#define CHUNK_BYTES (384 * 128)                // 384 rows x 64 bf16, dense 128B rows
#define SMEM_TOTAL  (4 * CHUNK_BYTES)          // 196608

// Scratch (device globals; no allocation allowed)
__device__ __nv_bfloat16 g_che[BATCH * DIM];
__device__ __nv_bfloat16 g_loc[BATCH * DIM];
__device__ float g_scale;
__device__ float g_shift;
__device__ float g_acc;
__device__ unsigned g_tile_ctr;

__device__ __forceinline__ uint32_t smem_u32(const void* p) {
    uint32_t a;
    asm("{ .reg .u64 t; cvta.to.shared.u64 t, %1; cvt.u32.u64 %0, t; }"
        : "=r"(a) : "l"(p));
    return a;
}

__device__ __forceinline__ void ldmatrix_x4(uint32_t* r, uint32_t addr) {
    asm volatile("ldmatrix.sync.aligned.m8n8.x4.shared.b16 {%0,%1,%2,%3}, [%4];"
                 : "=r"(r[0]), "=r"(r[1]), "=r"(r[2]), "=r"(r[3])
                 : "r"(addr));
}

__device__ __forceinline__ void mma_bf16(float* c, const uint32_t* a,
                                         uint32_t b0, uint32_t b1) {
    asm volatile(
        "mma.sync.aligned.m16n8k16.row.col.f32.bf16.bf16.f32 "
        "{%0,%1,%2,%3}, {%4,%5,%6,%7}, {%8,%9}, {%0,%1,%2,%3};"
        : "+f"(c[0]), "+f"(c[1]), "+f"(c[2]), "+f"(c[3])
        : "r"(a[0]), "r"(a[1]), "r"(a[2]), "r"(a[3]), "r"(b0), "r"(b1));
}

#define CP_ASYNC16(dst, src) \
    asm volatile("cp.async.cg.shared.global [%0], [%1], 16;" \
                 :: "r"(dst), "l"(src) : "memory")
#define CP_COMMIT() asm volatile("cp.async.commit_group;" ::: "memory")
#define CP_WAIT(n)  asm volatile("cp.async.wait_group %0;" :: "n"(n) : "memory")

// ---------------------------------------------------------------------------
// Kernel 1: row L2-normalize -> bf16 scratch. 2 rows per warp.
// ---------------------------------------------------------------------------
__global__ __launch_bounds__(256)
void norm_kernel(const float* __restrict__ loc,
                 const float* __restrict__ che,
                 const float* __restrict__ t_prime,
                 const float* __restrict__ b_in)
{
    int warp = threadIdx.x >> 5;
    int lane = threadIdx.x & 31;
    int row0 = (blockIdx.x << 4) + (warp << 1);

    #pragma unroll
    for (int rr = 0; rr < 2; rr++) {
        int row = row0 + rr;
        const float4* l4 = reinterpret_cast<const float4*>(loc + row * DIM) + lane * 2;
        const float4* c4 = reinterpret_cast<const float4*>(che + row * DIM) + lane * 2;
        float4 a0 = l4[0], a1 = l4[1];
        float4 b0 = c4[0], b1 = c4[1];

        float s0 = a0.x*a0.x + a0.y*a0.y + a0.z*a0.z + a0.w*a0.w
                 + a1.x*a1.x + a1.y*a1.y + a1.z*a1.z + a1.w*a1.w;
        float s1 = b0.x*b0.x + b0.y*b0.y + b0.z*b0.z + b0.w*b0.w
                 + b1.x*b1.x + b1.y*b1.y + b1.z*b1.z + b1.w*b1.w;
        #pragma unroll
        for (int o = 16; o > 0; o >>= 1) {
            s0 += __shfl_xor_sync(0xFFFFFFFFu, s0, o);
            s1 += __shfl_xor_sync(0xFFFFFFFFu, s1, o);
        }
        float r0 = rsqrtf(s0);
        float r1 = rsqrtf(s1);

        __nv_bfloat162 h[4];
        h[0] = __float22bfloat162_rn(make_float2(a0.x*r0, a0.y*r0));
        h[1] = __float22bfloat162_rn(make_float2(a0.z*r0, a0.w*r0));
        h[2] = __float22bfloat162_rn(make_float2(a1.x*r0, a1.y*r0));
        h[3] = __float22bfloat162_rn(make_float2(a1.z*r0, a1.w*r0));
        *reinterpret_cast<uint4*>(g_loc + row * DIM + lane * 8) =
            *reinterpret_cast<uint4*>(h);

        h[0] = __float22bfloat162_rn(make_float2(b0.x*r1, b0.y*r1));
        h[1] = __float22bfloat162_rn(make_float2(b0.z*r1, b0.w*r1));
        h[2] = __float22bfloat162_rn(make_float2(b1.x*r1, b1.y*r1));
        h[3] = __float22bfloat162_rn(make_float2(b1.z*r1, b1.w*r1));
        *reinterpret_cast<uint4*>(g_che + row * DIM + lane * 8) =
            *reinterpret_cast<uint4*>(h);
    }

    if (blockIdx.x == 0 && threadIdx.x == 0) {
        g_scale = expf(t_prime[0]);
        g_shift = b_in[0];
        g_acc = 0.0f;
        g_tile_ctr = 0u;
    }
}

// ---------------------------------------------------------------------------
// Prefetch one K=64 chunk (384 rows x 128B) into a swizzled ring buffer.
// 512 threads: 6 cp.async of 16B each. Lane-groups of 8 cover one full
// 128B row (all 32 banks) -> conflict-free stores.
// ---------------------------------------------------------------------------
__device__ __forceinline__ void prefetch_chunk(uint32_t dstBase, int m0, int n0,
                                               int chunk, int tid)
{
    const __nv_bfloat16* cheB = g_che + (size_t)m0 * DIM + chunk * 64;
    const __nv_bfloat16* locB = g_loc + (size_t)(n0 - TM) * DIM + chunk * 64;
    #pragma unroll
    for (int it = 0; it < 6; it++) {
        int idx = it * 512 + tid;            // 0..3071
        int r = idx >> 3;                    // 0..383
        int c = idx & 7;                     // 16B slot within 128B row
        uint32_t sw = (uint32_t)((c << 4) ^ ((r & 7) << 4));
        uint32_t dst = dstBase + (uint32_t)(r << 7) + sw;
        const __nv_bfloat16* src = (r < TM) ? cheB + (size_t)r * DIM + c * 8
                                            : locB + (size_t)r * DIM + c * 8;
        CP_ASYNC16(dst, src);
    }
}

// ---------------------------------------------------------------------------
// Compute one K=64 chunk: 4 ks steps over this warp's 64x32 fragment.
// A: 4 ldmatrix.x4 (m16k16 each); B: 2 ldmatrix.x4 (n16k16 each).
// ---------------------------------------------------------------------------
__device__ __forceinline__ void compute_chunk(uint32_t base,
                                              const uint32_t* aRB, const uint32_t* aX,
                                              const uint32_t* bRB, const uint32_t* bX,
                                              uint32_t kloA, uint32_t kloB,
                                              float (*c)[4])
{
    #pragma unroll
    for (int ks = 0; ks < 4; ks++) {
        uint32_t koff = (uint32_t)(ks << 5);   // 32B per k16 step
        uint32_t a[4][4], b[2][4];
        #pragma unroll
        for (int i = 0; i < 4; i++)
            ldmatrix_x4(a[i], base + aRB[i] + ((koff + kloA) ^ aX[i]));
        #pragma unroll
        for (int q = 0; q < 2; q++)
            ldmatrix_x4(b[q], base + bRB[q] + ((koff + kloB) ^ bX[q]));
        #pragma unroll
        for (int mt = 0; mt < 4; mt++) {
            #pragma unroll
            for (int nt = 0; nt < 4; nt++) {
                uint32_t b0 = b[nt >> 1][(nt & 1) ? 2 : 0];
                uint32_t b1 = b[nt >> 1][(nt & 1) ? 3 : 1];
                mma_bf16(c[mt * 4 + nt], a[mt], b0, b1);
            }
        }
    }
}

// ---------------------------------------------------------------------------
// Kernel 2: persistent 256x128-tile GEMM + fused softplus epilogue.
// 16 warps: wy = wid & 3 -> M rows [wy*64,+64), wx = wid>>2 -> N cols [wx*32,+32).
// ---------------------------------------------------------------------------
__global__ __launch_bounds__(512, 1)
void gemm_loss_kernel()
{
    extern __shared__ __align__(128) char smem[];
    const uint32_t sBase = smem_u32(smem);

    __shared__ unsigned sh_next;

    int tid = threadIdx.x;
    int wid = tid >> 5;
    int lane = tid & 31;

    int am = (wid & 3) * 64;
    int bn = (wid >> 2) * 32;

    // ldmatrix addressing components (dense 128B rows + SW128 xor swizzle)
    uint32_t aRB[4], aX[4], bRB[2], bX[2];
    #pragma unroll
    for (int i = 0; i < 4; i++) {
        int r = am + i * 16 + (lane & 15);
        aRB[i] = (uint32_t)(r << 7);
        aX[i]  = (uint32_t)((r & 7) << 4);
    }
    #pragma unroll
    for (int q = 0; q < 2; q++) {
        int r = TM + bn + q * 16 + ((lane >> 4) << 3) + (lane & 7);
        bRB[q] = (uint32_t)(r << 7);
        bX[q]  = (uint32_t)((r & 7) << 4);
    }
    uint32_t kloA = (uint32_t)((lane >> 4) << 4);
    uint32_t kloB = (uint32_t)(((lane >> 3) & 1) << 4);

    float c[16][4];
    #pragma unroll
    for (int i = 0; i < 16; i++)
        #pragma unroll
        for (int j = 0; j < 4; j++) c[i][j] = 0.0f;

    float scale = g_scale;
    float shift = g_shift;
    float acc = 0.0f;

    // ---- grab first tile ----
    if (tid == 0) sh_next = atomicAdd(&g_tile_ctr, 1u);
    __syncthreads();
    unsigned cur = sh_next;
    if (cur >= NTILES) return;

    int m0 = (int)(cur & 31) * TM;
    int n0 = (int)(cur >> 5) * TN;

    // warm ring: chunks 0,1,2 of first tile
    #pragma unroll
    for (int ch = 0; ch < 3; ch++) {
        prefetch_chunk(sBase + (uint32_t)(ch * CHUNK_BYTES), m0, n0, ch, tid);
        CP_COMMIT();
    }

    unsigned nxt = 0;
    for (;;) {
        int nm0 = 0, nn0 = 0;

        #pragma unroll
        for (int k = 0; k < 4; k++) {
            CP_WAIT(2);            // chunk k of cur complete (2 newer may pend)
            __syncthreads();       // data visible; old ring-slot data consumed

            if (k == 0) {
                if (tid == 0) sh_next = atomicAdd(&g_tile_ctr, 1u);
                prefetch_chunk(sBase + 3u * CHUNK_BYTES, m0, n0, 3, tid);
            } else {
                if (k == 1) {
                    nxt = sh_next;            // written at k=0, barrier at k=1
                    nm0 = (int)(nxt & 31) * TM;
                    nn0 = (int)(nxt >> 5) * TN;
                }
                if (nxt < NTILES)
                    prefetch_chunk(sBase + (uint32_t)((k - 1) * CHUNK_BYTES),
                                   nm0, nn0, k - 1, tid);
            }
            CP_COMMIT();

            compute_chunk(sBase + (uint32_t)(k * CHUNK_BYTES),
                          aRB, aX, bRB, bX, kloA, kloB, c);
        }

        // ---- epilogue for tile cur (next tile's loads stream meanwhile) ----
        {
            int rbase = m0 + am + (lane >> 2);
            int cbase = n0 + bn + (lane & 3) * 2;
            #pragma unroll
            for (int mt = 0; mt < 4; mt++) {
                #pragma unroll
                for (int nt = 0; nt < 4; nt++) {
                    float* cc = c[mt * 4 + nt];
                    int col0 = cbase + nt * 8;
                    #pragma unroll
                    for (int j = 0; j < 4; j++) {
                        int row = rbase + mt * 16 + ((j >> 1) << 3);
                        int col = col0 + (j & 1);
                        float z = fmaf(cc[j], scale, shift);
                        float v = (row == col) ? z : -z;     // y*z
                        float av = fabsf(v);
                        float e = __expf(-av);
                        float l;
                        if (e < 0.0625f) {
                            // log1p(e) ~ e - e^2/2 + e^3/3, |err| <= e^4/4
                            l = e * fmaf(e, fmaf(e, 0.33333333f, -0.5f), 1.0f);
                        } else {
                            l = log1pf(e);                   // near-diagonal only
                        }
                        acc += fmaxf(-v, 0.0f) + l;          // softplus(-v)
                        cc[j] = 0.0f;
                    }
                }
            }
        }

        if (nxt >= NTILES) break;
        cur = nxt; m0 = nm0; n0 = nn0;
    }

    // ---- CTA reduce + one atomic ----
    #pragma unroll
    for (int o = 16; o > 0; o >>= 1)
        acc += __shfl_xor_sync(0xFFFFFFFFu, acc, o);
    __shared__ float shred[16];
    if (lane == 0) shred[wid] = acc;
    __syncthreads();
    if (tid == 0) {
        float s = 0.f;
        #pragma unroll
        for (int i = 0; i < 16; i++) s += shred[i];
        atomicAdd(&g_acc, s);
    }
}

// ---------------------------------------------------------------------------
// g_acc = sum_ij -log_sigmoid(y*z)  ->  loss = +g_acc/B
// ---------------------------------------------------------------------------
__global__ void finalize_kernel(float* out)
{
    out[0] = g_acc * (1.0f / (float)BATCH);
}

// ---------------------------------------------------------------------------
extern "C" void kernel_launch(void* const* d_in, const int* in_sizes, int n_in,
                              void* d_out, int out_size)
{
    const float* loc = (const float*)d_in[0];
    const float* che = (const float*)d_in[1];
    const float* tp  = (const float*)d_in[2];
    const float* bb  = (const float*)d_in[3];
    float* out = (float*)d_out;

    norm_kernel<<<BATCH / 16, 256>>>(loc, che, tp, bb);

    static bool attr_set = false;
    if (!attr_set) {
        cudaFuncSetAttribute(gemm_loss_kernel,
                             cudaFuncAttributeMaxDynamicSharedMemorySize, SMEM_TOTAL);
        attr_set = true;
    }
    gemm_loss_kernel<<<152, 512, SMEM_TOTAL>>>();

    finalize_kernel<<<1, 1>>>(out);
}